// round 7
// baseline (speedup 1.0000x reference)
#include <cuda_runtime.h>
#include <cuda_bf16.h>
#include <cstdint>

// Problem constants
constexpr int HID   = 256;
constexpr int NROWS = 5151;
constexpr int B     = 8;
constexpr int T     = 2048;
constexpr int NLAYERS = 3;

// Density kernel tiling: 40 rows/block (two 20-row groups), 2 cols/thread
constexpr int RB2     = 40;                       // rows per block
constexpr int RG      = 20;                       // rows per thread-group
constexpr int D_TPB   = 256;
constexpr int DB_BLKS = (NROWS + RB2 - 1) / RB2;  // 129
constexpr int KU      = 8;                        // k-prefetch depth

// Chunked scan config
constexpr int C   = 8;
constexpr int TC  = T / C;        // 256
constexpr int P1_TPB = 128;
constexpr int P1_BLK = (NROWS + P1_TPB - 1) / P1_TPB;   // 41
constexpr int P2_TPB = 64;
constexpr int PPT    = 4;
constexpr int P2_PTS = P2_TPB * PPT;                     // 256
constexpr int P2_BLK = (NROWS + P2_PTS - 1) / P2_PTS;    // 21
constexpr int NW2    = P2_BLK * (P2_TPB / 32);           // 42

// Output section offsets
constexpr int OFF_BNORM = 0;
constexpr int OFF_DENSB = 16384;
constexpr int OFF_M     = 57592;
constexpr int OFF_IS    = 73976;
constexpr int OFF_MESHB = 115184;

// Scratch (device globals)
__device__ float  g_density[DB_BLKS * RB2];
__device__ float  g_inv_sum;
__device__ float2 g_ab[(size_t)B * (C - 1) * NROWS];
__device__ float  g_sstart[(size_t)B * C * NROWS];
__device__ float  g_part[(size_t)B * NW2 * T];

typedef unsigned long long u64;

__device__ __forceinline__ float tanh_fast(float x) {
    float y;
    asm("tanh.approx.f32 %0, %1;" : "=f"(y) : "f"(x));
    return y;
}
__device__ __forceinline__ u64 pack2(float lo, float hi) {
    u64 r; asm("mov.b64 %0, {%1, %2};" : "=l"(r) : "f"(lo), "f"(hi)); return r;
}
__device__ __forceinline__ void unpack2(u64 v, float& lo, float& hi) {
    asm("mov.b64 {%0, %1}, %2;" : "=f"(lo), "=f"(hi) : "l"(v));
}
__device__ __forceinline__ u64 fma2(u64 a, u64 b, u64 c) {
    u64 d; asm("fma.rn.f32x2 %0, %1, %2, %3;" : "=l"(d) : "l"(a), "l"(b), "l"(c)); return d;
}

// ---------------------------------------------------------------------------
// Density MLP: 2 output columns per thread (j, j+128), 20-row slice per
// thread.  Per k: 5 broadcast LDS.128 feed 20 FFMA2 (1:4 vs old 1:2) --
// moves the bottleneck from the L1/shared pipe (77%) to the FMA pipe.
// ---------------------------------------------------------------------------
__global__ __launch_bounds__(D_TPB) void density_kernel(
    const float* __restrict__ mesh, const float* __restrict__ Win,
    const float* __restrict__ bin,  const float* __restrict__ Wblk,
    const float* __restrict__ bblk, const float* __restrict__ Wout,
    const float* __restrict__ bout)
{
    __shared__ float cur[HID * RB2];   // [k][r], 40 KB
    const int tid  = threadIdx.x;
    const int j    = tid & 127;        // column pair (j, j+128)
    const int g    = tid >> 7;         // row group 0/1
    const int r0   = g * RG;
    const int row0 = blockIdx.x * RB2;

    // ---- input layer ----
    {
        const float w0a = Win[j],       w1a = Win[HID + j],       ba = bin[j];
        const float w0b = Win[j + 128], w1b = Win[HID + j + 128], bb = bin[j + 128];
        #pragma unroll
        for (int r = 0; r < RG; r++) {
            const int rr = row0 + r0 + r;
            float m0 = 0.f, m1 = 0.f;
            if (rr < NROWS) { m0 = mesh[2 * rr]; m1 = mesh[2 * rr + 1]; }
            cur[j * RB2 + r0 + r]         = fmaxf(fmaf(m1, w1a, fmaf(m0, w0a, ba)), 0.f);
            cur[(j + 128) * RB2 + r0 + r] = fmaxf(fmaf(m1, w1b, fmaf(m0, w0b, bb)), 0.f);
        }
    }
    __syncthreads();

    // ---- residual layers ----
    for (int l = 0; l < NLAYERS; l++) {
        const float* W0 = Wblk + (size_t)l * HID * HID + j;
        const float* W1 = W0 + 128;
        const float  bl0 = bblk[l * HID + j];
        const float  bl1 = bblk[l * HID + j + 128];

        u64 acc0[RG / 2], acc1[RG / 2];
        #pragma unroll
        for (int q = 0; q < RG / 2; q++) { acc0[q] = 0ull; acc1[q] = 0ull; }

        float wbuf0[KU], wbuf1[KU];
        #pragma unroll
        for (int kk = 0; kk < KU; kk++) {
            wbuf0[kk] = W0[(size_t)kk * HID];
            wbuf1[kk] = W1[(size_t)kk * HID];
        }

        #pragma unroll 1
        for (int k0 = 0; k0 < HID; k0 += KU) {
            float wn0[KU], wn1[KU];
            const bool more = (k0 + KU) < HID;
            #pragma unroll
            for (int kk = 0; kk < KU; kk++) {
                wn0[kk] = more ? W0[(size_t)(k0 + KU + kk) * HID] : 0.f;
                wn1[kk] = more ? W1[(size_t)(k0 + KU + kk) * HID] : 0.f;
            }

            #pragma unroll
            for (int kk = 0; kk < KU; kk++) {
                const u64 w20 = pack2(wbuf0[kk], wbuf0[kk]);
                const u64 w21 = pack2(wbuf1[kk], wbuf1[kk]);
                const ulonglong2* hp =
                    reinterpret_cast<const ulonglong2*>(cur + (k0 + kk) * RB2 + r0);
                #pragma unroll
                for (int q = 0; q < RG / 4; q++) {     // 5 broadcast LDS.128
                    const ulonglong2 h2 = hp[q];
                    acc0[2 * q]     = fma2(h2.x, w20, acc0[2 * q]);
                    acc0[2 * q + 1] = fma2(h2.y, w20, acc0[2 * q + 1]);
                    acc1[2 * q]     = fma2(h2.x, w21, acc1[2 * q]);
                    acc1[2 * q + 1] = fma2(h2.y, w21, acc1[2 * q + 1]);
                }
            }
            #pragma unroll
            for (int kk = 0; kk < KU; kk++) { wbuf0[kk] = wn0[kk]; wbuf1[kk] = wn1[kk]; }
        }

        // residual add: read old h (pre-overwrite), then barrier, then write
        float hn0[RG], hn1[RG];
        #pragma unroll
        for (int q = 0; q < RG / 2; q++) {
            float a0, a1, b0, b1;
            unpack2(acc0[q], a0, a1);
            unpack2(acc1[q], b0, b1);
            hn0[2 * q]     = cur[j * RB2 + r0 + 2 * q]             + fmaxf(a0 + bl0, 0.f);
            hn0[2 * q + 1] = cur[j * RB2 + r0 + 2 * q + 1]         + fmaxf(a1 + bl0, 0.f);
            hn1[2 * q]     = cur[(j + 128) * RB2 + r0 + 2 * q]     + fmaxf(b0 + bl1, 0.f);
            hn1[2 * q + 1] = cur[(j + 128) * RB2 + r0 + 2 * q + 1] + fmaxf(b1 + bl1, 0.f);
        }
        __syncthreads();
        #pragma unroll
        for (int r = 0; r < RG; r += 4) {
            *reinterpret_cast<float4*>(cur + j * RB2 + r0 + r) =
                make_float4(hn0[r], hn0[r + 1], hn0[r + 2], hn0[r + 3]);
            *reinterpret_cast<float4*>(cur + (j + 128) * RB2 + r0 + r) =
                make_float4(hn1[r], hn1[r + 1], hn1[r + 2], hn1[r + 3]);
        }
        __syncthreads();
    }

    // ---- output layer: scale by Wout, tree-reduce over k ----
    {
        const float wo0 = Wout[j], wo1 = Wout[j + 128];
        #pragma unroll
        for (int r = 0; r < RG; r++) {
            cur[j * RB2 + r0 + r]         *= wo0;
            cur[(j + 128) * RB2 + r0 + r] *= wo1;
        }
        __syncthreads();
        if (tid < RB2) {
            float s0 = bout[0], s1 = 0.f, s2 = 0.f, s3 = 0.f;
            #pragma unroll 4
            for (int k = 0; k < HID; k += 4) {
                s0 += cur[(k + 0) * RB2 + tid];
                s1 += cur[(k + 1) * RB2 + tid];
                s2 += cur[(k + 2) * RB2 + tid];
                s3 += cur[(k + 3) * RB2 + tid];
            }
            const float s  = (s0 + s1) + (s2 + s3);
            const int   rr = row0 + tid;
            if (rr < NROWS)
                g_density[rr] = __fdividef(1.f, 1.f + __expf(-s));
        }
    }
}

// ---------------------------------------------------------------------------
// 1/sum(density): single block, float4-vectorized, deterministic
// ---------------------------------------------------------------------------
__global__ __launch_bounds__(1024) void sum_kernel()
{
    __shared__ float sh[32];
    const float4* p4 = reinterpret_cast<const float4*>(g_density);
    float s = 0.f;
    for (int i = threadIdx.x; i < NROWS / 4; i += 1024) {
        const float4 v = p4[i];
        s += (v.x + v.y) + (v.z + v.w);
    }
    if (threadIdx.x < (NROWS & 3))
        s += g_density[(NROWS & ~3) + threadIdx.x];
    #pragma unroll
    for (int o = 16; o; o >>= 1) s += __shfl_xor_sync(0xffffffffu, s, o);
    if ((threadIdx.x & 31) == 0) sh[threadIdx.x >> 5] = s;
    __syncthreads();
    if (threadIdx.x < 32) {
        s = sh[threadIdx.x];
        #pragma unroll
        for (int o = 16; o; o >>= 1) s += __shfl_xor_sync(0xffffffffu, s, o);
        if (threadIdx.x == 0) g_inv_sum = __fdividef(1.f, s);
    }
}

// ---------------------------------------------------------------------------
// Pass 1: per-chunk composed affine transform
// ---------------------------------------------------------------------------
__global__ __launch_bounds__(P1_TPB) void pass1_kernel(
    const float* __restrict__ dec, const float* __restrict__ y0,
    const float* __restrict__ mesh)
{
    __shared__ float hs[TC];
    const int b  = blockIdx.z;
    const int ck = blockIdx.y;
    const int i  = blockIdx.x * P1_TPB + threadIdx.x;
    const int t0 = ck * TC;

    for (int t = threadIdx.x; t < TC; t += P1_TPB) hs[t] = dec[b * T + t0 + t];

    float na2 = 0.f, nb2 = 0.f;
    if (i < NROWS) {
        nb2 = -mesh[2 * i] * 500.f;
        na2 = -mesh[2 * i + 1] * 500.f;
    }
    __syncthreads();

    float hprev = (ck == 0) ? y0[b] : dec[b * T + t0 - 1];
    float A = 1.f, Bc = 0.f;

    #pragma unroll 4
    for (int t = 0; t < TC; t++) {
        const float ht  = hs[t];
        const bool  inc = (ht >= hprev);
        hprev = ht;
        const float thr = inc ? na2 : nb2;
        const float c2  = inc ? 0.5f : -0.5f;
        const float u   = tanh_fast(fmaf(ht, 500.f, thr));
        const float a   = fmaf(-c2, u, 0.5f);
        const float bb  = fmaf(0.5f, u, c2);
        A  = A * a;
        Bc = fmaf(a, Bc, bb);
    }
    if (i < NROWS)
        g_ab[((size_t)b * (C - 1) + ck) * NROWS + i] = make_float2(A, Bc);
}

// ---------------------------------------------------------------------------
// Compose chunk transforms -> chunk start states
// ---------------------------------------------------------------------------
__global__ __launch_bounds__(256) void compose_kernel(const float* __restrict__ s0_all)
{
    const int idx = blockIdx.x * blockDim.x + threadIdx.x;
    if (idx >= B * NROWS) return;
    const int b = idx / NROWS;
    const int i = idx - b * NROWS;
    float s = s0_all[idx];
    g_sstart[((size_t)b * C + 0) * NROWS + i] = s;
    #pragma unroll
    for (int ck = 0; ck < C - 1; ck++) {
        const float2 ab = g_ab[((size_t)b * (C - 1) + ck) * NROWS + i];
        s = fmaf(ab.x, s, ab.y);
        g_sstart[((size_t)b * C + ck + 1) * NROWS + i] = s;
    }
}

// ---------------------------------------------------------------------------
// Pass 2: replay chunks, fused density dot
// ---------------------------------------------------------------------------
__global__ __launch_bounds__(P2_TPB) void pass2_kernel(
    const float* __restrict__ dec, const float* __restrict__ y0,
    const float* __restrict__ mesh)
{
    __shared__ float hs[TC];
    const int b   = blockIdx.z;
    const int ck  = blockIdx.y;
    const int t0  = ck * TC;
    const int i0  = blockIdx.x * P2_PTS;
    const int w   = threadIdx.x >> 5;
    const int lane= threadIdx.x & 31;

    for (int t = threadIdx.x; t < TC; t += P2_TPB) hs[t] = dec[b * T + t0 + t];

    float na2[PPT], nb2[PPT], d[PPT], s[PPT];
    #pragma unroll
    for (int p = 0; p < PPT; p++) {
        const int i = i0 + w * (32 * PPT) + p * 32 + lane;
        if (i < NROWS) {
            nb2[p] = -mesh[2 * i] * 500.f;
            na2[p] = -mesh[2 * i + 1] * 500.f;
            d[p]   = g_density[i];
            s[p]   = g_sstart[((size_t)b * C + ck) * NROWS + i];
        } else { nb2[p] = 0.f; na2[p] = 0.f; d[p] = 0.f; s[p] = 0.f; }
    }
    __syncthreads();

    float hprev = (ck == 0) ? y0[b] : dec[b * T + t0 - 1];
    float* mypart = g_part + ((size_t)(b * NW2 + blockIdx.x * 2 + w)) * T + t0;

    #pragma unroll 2
    for (int t = 0; t < TC; t++) {
        const float ht  = hs[t];
        const bool  inc = (ht >= hprev);
        hprev = ht;
        const float c2  = inc ? 0.5f : -0.5f;
        float acc = 0.f;
        #pragma unroll
        for (int p = 0; p < PPT; p++) {
            const float thr = inc ? na2[p] : nb2[p];
            const float u   = tanh_fast(fmaf(ht, 500.f, thr));
            const float a   = fmaf(-c2, u, 0.5f);
            const float bb  = fmaf(0.5f, u, c2);
            s[p] = fmaf(a, s[p], bb);
            acc  = fmaf(d[p], s[p], acc);
        }
        #pragma unroll
        for (int o = 16; o; o >>= 1) acc += __shfl_xor_sync(0xffffffffu, acc, o);
        if (lane == 0) mypart[t] = acc;
    }
}

// ---------------------------------------------------------------------------
// Reduce warp partials -> m, b_norm
// ---------------------------------------------------------------------------
__global__ __launch_bounds__(256) void finalize_kernel(float* __restrict__ out)
{
    const int idx = blockIdx.x * blockDim.x + threadIdx.x;
    if (idx >= B * T) return;
    const int b = idx / T;
    const int t = idx - b * T;
    const float* p = g_part + (size_t)b * NW2 * T + t;
    float s0 = 0.f, s1 = 0.f;
    #pragma unroll 2
    for (int wv = 0; wv < NW2; wv += 2) {
        s0 += p[(size_t)wv * T];
        s1 += p[(size_t)(wv + 1) * T];
    }
    const float m = (s0 + s1) * g_inv_sum;
    out[OFF_BNORM + idx] = fmaf(0.5f, m, 0.5f);
    out[OFF_M + idx]     = m;
}

// ---------------------------------------------------------------------------
// fill_mesh: input-only sections; fill_dens: density broadcast
// ---------------------------------------------------------------------------
__global__ __launch_bounds__(256) void fill_mesh_kernel(
    const float* __restrict__ s0_all, const float* __restrict__ mesh,
    float* __restrict__ out)
{
    const int i = blockIdx.x * blockDim.x + threadIdx.x;
    if (i < B * NROWS)
        out[OFF_IS + i] = s0_all[i];
    if (i < B * NROWS * 2)
        out[OFF_MESHB + i] = mesh[i % (2 * NROWS)];
}

__global__ __launch_bounds__(256) void fill_dens_kernel(float* __restrict__ out)
{
    const int i = blockIdx.x * blockDim.x + threadIdx.x;
    if (i < B * NROWS)
        out[OFF_DENSB + i] = g_density[i % NROWS];
}

// ---------------------------------------------------------------------------
// Launch order keeps density at slot #4 (ncu profiles launch #4).
// ---------------------------------------------------------------------------
extern "C" void kernel_launch(void* const* d_in, const int* in_sizes, int n_in,
                              void* d_out, int out_size)
{
    (void)in_sizes; (void)n_in; (void)out_size;
    const float* dec  = (const float*)d_in[1];
    const float* init = (const float*)d_in[2];
    const float* y0   = (const float*)d_in[3];
    const float* mesh = (const float*)d_in[4];
    const float* Win  = (const float*)d_in[5];
    const float* bin  = (const float*)d_in[6];
    const float* Wblk = (const float*)d_in[7];
    const float* bblk = (const float*)d_in[8];
    const float* Wout = (const float*)d_in[9];
    const float* bout = (const float*)d_in[10];
    float* out = (float*)d_out;

    pass1_kernel<<<dim3(P1_BLK, C - 1, B), P1_TPB>>>(dec, y0, mesh);
    compose_kernel<<<(B * NROWS + 255) / 256, 256>>>(init);
    fill_mesh_kernel<<<(B * NROWS * 2 + 255) / 256, 256>>>(init, mesh, out);
    density_kernel<<<DB_BLKS, D_TPB>>>(mesh, Win, bin, Wblk, bblk, Wout, bout);
    sum_kernel<<<1, 1024>>>();
    fill_dens_kernel<<<(B * NROWS + 255) / 256, 256>>>(out);
    pass2_kernel<<<dim3(P2_BLK, C, B), P2_TPB>>>(dec, y0, mesh);
    finalize_kernel<<<(B * T + 255) / 256, 256>>>(out);
}

// round 8
// speedup vs baseline: 1.1710x; 1.1710x over previous
#include <cuda_runtime.h>
#include <cuda_bf16.h>
#include <cstdint>

// Problem constants
constexpr int HID   = 256;
constexpr int NROWS = 5151;
constexpr int B     = 8;
constexpr int T     = 2048;
constexpr int NLAYERS = 3;

// Density kernel tiling (R6-best config): 144 blocks ~= 1/SM
constexpr int RB      = 36;
constexpr int DB_BLKS = (NROWS + RB - 1) / RB;   // 144
constexpr int KU      = 8;                        // k-prefetch depth

// Chunked scan config
constexpr int C   = 8;
constexpr int TC  = T / C;        // 256
constexpr int P1_TPB = 128;
constexpr int P1_BLK = (NROWS + P1_TPB - 1) / P1_TPB;   // 41
constexpr int P2_TPB = 64;
constexpr int PPT    = 8;                                // 8 points/thread
constexpr int P2_PTS = P2_TPB * PPT;                     // 512
constexpr int P2_BLK = (NROWS + P2_PTS - 1) / P2_PTS;    // 11
constexpr int NW2    = P2_BLK * (P2_TPB / 32);           // 22

// Output section offsets
constexpr int OFF_BNORM = 0;
constexpr int OFF_DENSB = 16384;
constexpr int OFF_M     = 57592;
constexpr int OFF_IS    = 73976;
constexpr int OFF_MESHB = 115184;

// Scratch (device globals)
__device__ float  g_density[DB_BLKS * RB];
__device__ float  g_inv_sum;
__device__ float2 g_ab[(size_t)B * (C - 1) * NROWS];
__device__ float  g_sstart[(size_t)B * C * NROWS];
__device__ float  g_part[(size_t)B * NW2 * T];

typedef unsigned long long u64;

__device__ __forceinline__ float tanh_fast(float x) {
    float y;
    asm("tanh.approx.f32 %0, %1;" : "=f"(y) : "f"(x));
    return y;
}
__device__ __forceinline__ u64 pack2(float lo, float hi) {
    u64 r; asm("mov.b64 %0, {%1, %2};" : "=l"(r) : "f"(lo), "f"(hi)); return r;
}
__device__ __forceinline__ void unpack2(u64 v, float& lo, float& hi) {
    asm("mov.b64 {%0, %1}, %2;" : "=f"(lo), "=f"(hi) : "l"(v));
}
__device__ __forceinline__ u64 fma2(u64 a, u64 b, u64 c) {
    u64 d; asm("fma.rn.f32x2 %0, %1, %2, %3;" : "=l"(d) : "l"(a), "l"(b), "l"(c)); return d;
}

// ---------------------------------------------------------------------------
// Density MLP: exact R6-best version.  h TRANSPOSED in smem [k][r]; KU=8
// software-pipelined weight prefetch + packed fma.rn.f32x2.
// ---------------------------------------------------------------------------
__global__ __launch_bounds__(HID) void density_kernel(
    const float* __restrict__ mesh, const float* __restrict__ Win,
    const float* __restrict__ bin,  const float* __restrict__ Wblk,
    const float* __restrict__ bblk, const float* __restrict__ Wout,
    const float* __restrict__ bout)
{
    __shared__ float cur[HID * RB];   // [k][r], 36 KB
    const int j    = threadIdx.x;
    const int row0 = blockIdx.x * RB;
    float hcur[RB];

    // ---- input layer ----
    {
        const float w0 = Win[j];
        const float w1 = Win[HID + j];
        const float bj = bin[j];
        #pragma unroll
        for (int r = 0; r < RB; r++) {
            const int rr = row0 + r;
            float m0 = 0.f, m1 = 0.f;
            if (rr < NROWS) { m0 = mesh[2 * rr]; m1 = mesh[2 * rr + 1]; }
            hcur[r] = fmaxf(fmaf(m1, w1, fmaf(m0, w0, bj)), 0.f);
        }
    }
    #pragma unroll
    for (int r = 0; r < RB; r += 4)
        *reinterpret_cast<float4*>(cur + j * RB + r) =
            make_float4(hcur[r], hcur[r + 1], hcur[r + 2], hcur[r + 3]);
    __syncthreads();

    // ---- residual layers ----
    for (int l = 0; l < NLAYERS; l++) {
        const float* Wj = Wblk + (size_t)l * HID * HID + j;
        const float  bl = bblk[l * HID + j];

        u64 acc2[RB / 2];
        #pragma unroll
        for (int q = 0; q < RB / 2; q++) acc2[q] = 0ull;

        float wbuf[KU];
        #pragma unroll
        for (int kk = 0; kk < KU; kk++) wbuf[kk] = Wj[(size_t)kk * HID];

        #pragma unroll 1
        for (int k0 = 0; k0 < HID; k0 += KU) {
            float wn[KU];
            const bool more = (k0 + KU) < HID;
            #pragma unroll
            for (int kk = 0; kk < KU; kk++)
                wn[kk] = more ? Wj[(size_t)(k0 + KU + kk) * HID] : 0.f;

            #pragma unroll
            for (int kk = 0; kk < KU; kk++) {
                const u64 w2 = pack2(wbuf[kk], wbuf[kk]);
                const ulonglong2* hp =
                    reinterpret_cast<const ulonglong2*>(cur + (k0 + kk) * RB);
                #pragma unroll
                for (int q = 0; q < RB / 4; q++) {          // 9 LDS.128 per k
                    const ulonglong2 h2 = hp[q];
                    acc2[2 * q]     = fma2(h2.x, w2, acc2[2 * q]);
                    acc2[2 * q + 1] = fma2(h2.y, w2, acc2[2 * q + 1]);
                }
            }
            #pragma unroll
            for (int kk = 0; kk < KU; kk++) wbuf[kk] = wn[kk];
        }

        #pragma unroll
        for (int q = 0; q < RB / 2; q++) {
            float a0, a1;
            unpack2(acc2[q], a0, a1);
            hcur[2 * q]     += fmaxf(a0 + bl, 0.f);
            hcur[2 * q + 1] += fmaxf(a1 + bl, 0.f);
        }

        __syncthreads();
        #pragma unroll
        for (int r = 0; r < RB; r += 4)
            *reinterpret_cast<float4*>(cur + j * RB + r) =
                make_float4(hcur[r], hcur[r + 1], hcur[r + 2], hcur[r + 3]);
        __syncthreads();
    }

    // ---- output layer ----
    {
        const float wo = Wout[j];
        #pragma unroll
        for (int r = 0; r < RB; r += 4)
            *reinterpret_cast<float4*>(cur + j * RB + r) =
                make_float4(hcur[r] * wo, hcur[r + 1] * wo, hcur[r + 2] * wo, hcur[r + 3] * wo);
        __syncthreads();
        if (j < RB) {
            float s0 = bout[0], s1 = 0.f, s2 = 0.f, s3 = 0.f;
            #pragma unroll 4
            for (int k = 0; k < HID; k += 4) {
                s0 += cur[(k + 0) * RB + j];
                s1 += cur[(k + 1) * RB + j];
                s2 += cur[(k + 2) * RB + j];
                s3 += cur[(k + 3) * RB + j];
            }
            const float s  = (s0 + s1) + (s2 + s3);
            const int   rr = row0 + j;
            if (rr < NROWS)
                g_density[rr] = __fdividef(1.f, 1.f + __expf(-s));
        }
    }
}

// ---------------------------------------------------------------------------
// 1/sum(density): single block, float4-vectorized, deterministic
// ---------------------------------------------------------------------------
__global__ __launch_bounds__(1024) void sum_kernel()
{
    __shared__ float sh[32];
    const float4* p4 = reinterpret_cast<const float4*>(g_density);
    float s = 0.f;
    for (int i = threadIdx.x; i < NROWS / 4; i += 1024) {
        const float4 v = p4[i];
        s += (v.x + v.y) + (v.z + v.w);
    }
    if (threadIdx.x < (NROWS & 3))
        s += g_density[(NROWS & ~3) + threadIdx.x];
    #pragma unroll
    for (int o = 16; o; o >>= 1) s += __shfl_xor_sync(0xffffffffu, s, o);
    if ((threadIdx.x & 31) == 0) sh[threadIdx.x >> 5] = s;
    __syncthreads();
    if (threadIdx.x < 32) {
        s = sh[threadIdx.x];
        #pragma unroll
        for (int o = 16; o; o >>= 1) s += __shfl_xor_sync(0xffffffffu, s, o);
        if (threadIdx.x == 0) g_inv_sum = __fdividef(1.f, s);
    }
}

// ---------------------------------------------------------------------------
// Pass 1: per-chunk composed affine transform
// ---------------------------------------------------------------------------
__global__ __launch_bounds__(P1_TPB) void pass1_kernel(
    const float* __restrict__ dec, const float* __restrict__ y0,
    const float* __restrict__ mesh)
{
    __shared__ float hs[TC];
    const int b  = blockIdx.z;
    const int ck = blockIdx.y;
    const int i  = blockIdx.x * P1_TPB + threadIdx.x;
    const int t0 = ck * TC;

    for (int t = threadIdx.x; t < TC; t += P1_TPB) hs[t] = dec[b * T + t0 + t];

    float na2 = 0.f, nb2 = 0.f;
    if (i < NROWS) {
        nb2 = -mesh[2 * i] * 500.f;
        na2 = -mesh[2 * i + 1] * 500.f;
    }
    __syncthreads();

    float hprev = (ck == 0) ? y0[b] : dec[b * T + t0 - 1];
    float A = 1.f, Bc = 0.f;

    #pragma unroll 4
    for (int t = 0; t < TC; t++) {
        const float ht  = hs[t];
        const bool  inc = (ht >= hprev);
        hprev = ht;
        const float thr = inc ? na2 : nb2;
        const float c2  = inc ? 0.5f : -0.5f;
        const float u   = tanh_fast(fmaf(ht, 500.f, thr));
        const float a   = fmaf(-c2, u, 0.5f);
        const float bb  = fmaf(0.5f, u, c2);
        A  = A * a;
        Bc = fmaf(a, Bc, bb);
    }
    if (i < NROWS)
        g_ab[((size_t)b * (C - 1) + ck) * NROWS + i] = make_float2(A, Bc);
}

// ---------------------------------------------------------------------------
// Compose chunk transforms -> chunk start states
// ---------------------------------------------------------------------------
__global__ __launch_bounds__(256) void compose_kernel(const float* __restrict__ s0_all)
{
    const int idx = blockIdx.x * blockDim.x + threadIdx.x;
    if (idx >= B * NROWS) return;
    const int b = idx / NROWS;
    const int i = idx - b * NROWS;
    float s = s0_all[idx];
    g_sstart[((size_t)b * C + 0) * NROWS + i] = s;
    #pragma unroll
    for (int ck = 0; ck < C - 1; ck++) {
        const float2 ab = g_ab[((size_t)b * (C - 1) + ck) * NROWS + i];
        s = fmaf(ab.x, s, ab.y);
        g_sstart[((size_t)b * C + ck + 1) * NROWS + i] = s;
    }
}

// ---------------------------------------------------------------------------
// Pass 2: replay chunks, fused density dot.  PPT=8: shuffle cost per point
// halves, 8-wide ILP covers the SHFL/MUFU latency chain.
// ---------------------------------------------------------------------------
__global__ __launch_bounds__(P2_TPB) void pass2_kernel(
    const float* __restrict__ dec, const float* __restrict__ y0,
    const float* __restrict__ mesh)
{
    __shared__ float hs[TC];
    const int b   = blockIdx.z;
    const int ck  = blockIdx.y;
    const int t0  = ck * TC;
    const int i0  = blockIdx.x * P2_PTS;
    const int w   = threadIdx.x >> 5;
    const int lane= threadIdx.x & 31;

    for (int t = threadIdx.x; t < TC; t += P2_TPB) hs[t] = dec[b * T + t0 + t];

    float na2[PPT], nb2[PPT], d[PPT], s[PPT];
    #pragma unroll
    for (int p = 0; p < PPT; p++) {
        const int i = i0 + w * (32 * PPT) + p * 32 + lane;
        if (i < NROWS) {
            nb2[p] = -mesh[2 * i] * 500.f;
            na2[p] = -mesh[2 * i + 1] * 500.f;
            d[p]   = g_density[i];
            s[p]   = g_sstart[((size_t)b * C + ck) * NROWS + i];
        } else { nb2[p] = 0.f; na2[p] = 0.f; d[p] = 0.f; s[p] = 0.f; }
    }
    __syncthreads();

    float hprev = (ck == 0) ? y0[b] : dec[b * T + t0 - 1];
    float* mypart = g_part + ((size_t)(b * NW2 + blockIdx.x * 2 + w)) * T + t0;

    #pragma unroll 2
    for (int t = 0; t < TC; t++) {
        const float ht  = hs[t];
        const bool  inc = (ht >= hprev);
        hprev = ht;
        const float c2  = inc ? 0.5f : -0.5f;
        float acc = 0.f;
        #pragma unroll
        for (int p = 0; p < PPT; p++) {
            const float thr = inc ? na2[p] : nb2[p];
            const float u   = tanh_fast(fmaf(ht, 500.f, thr));
            const float a   = fmaf(-c2, u, 0.5f);
            const float bb  = fmaf(0.5f, u, c2);
            s[p] = fmaf(a, s[p], bb);
            acc  = fmaf(d[p], s[p], acc);
        }
        #pragma unroll
        for (int o = 16; o; o >>= 1) acc += __shfl_xor_sync(0xffffffffu, acc, o);
        if (lane == 0) mypart[t] = acc;
    }
}

// ---------------------------------------------------------------------------
// Reduce warp partials -> m, b_norm
// ---------------------------------------------------------------------------
__global__ __launch_bounds__(256) void finalize_kernel(float* __restrict__ out)
{
    const int idx = blockIdx.x * blockDim.x + threadIdx.x;
    if (idx >= B * T) return;
    const int b = idx / T;
    const int t = idx - b * T;
    const float* p = g_part + (size_t)b * NW2 * T + t;
    float s0 = 0.f, s1 = 0.f;
    #pragma unroll 2
    for (int wv = 0; wv < NW2; wv += 2) {
        s0 += p[(size_t)wv * T];
        s1 += p[(size_t)(wv + 1) * T];
    }
    const float m = (s0 + s1) * g_inv_sum;
    out[OFF_BNORM + idx] = fmaf(0.5f, m, 0.5f);
    out[OFF_M + idx]     = m;
}

// ---------------------------------------------------------------------------
// fill_mesh: input-only sections; fill_dens: density broadcast
// ---------------------------------------------------------------------------
__global__ __launch_bounds__(256) void fill_mesh_kernel(
    const float* __restrict__ s0_all, const float* __restrict__ mesh,
    float* __restrict__ out)
{
    const int i = blockIdx.x * blockDim.x + threadIdx.x;
    if (i < B * NROWS)
        out[OFF_IS + i] = s0_all[i];
    if (i < B * NROWS * 2)
        out[OFF_MESHB + i] = mesh[i % (2 * NROWS)];
}

__global__ __launch_bounds__(256) void fill_dens_kernel(float* __restrict__ out)
{
    const int i = blockIdx.x * blockDim.x + threadIdx.x;
    if (i < B * NROWS)
        out[OFF_DENSB + i] = g_density[i % NROWS];
}

// ---------------------------------------------------------------------------
// Fork-join: density (FMA-bound) on main stream, pass1+compose (MUFU-bound)
// on a side stream; join before pass2.  pass2 is launch #4 for ncu.
// ---------------------------------------------------------------------------
extern "C" void kernel_launch(void* const* d_in, const int* in_sizes, int n_in,
                              void* d_out, int out_size)
{
    (void)in_sizes; (void)n_in; (void)out_size;
    const float* dec  = (const float*)d_in[1];
    const float* init = (const float*)d_in[2];
    const float* y0   = (const float*)d_in[3];
    const float* mesh = (const float*)d_in[4];
    const float* Win  = (const float*)d_in[5];
    const float* bin  = (const float*)d_in[6];
    const float* Wblk = (const float*)d_in[7];
    const float* bblk = (const float*)d_in[8];
    const float* Wout = (const float*)d_in[9];
    const float* bout = (const float*)d_in[10];
    float* out = (float*)d_out;

    cudaStream_t side;
    cudaEvent_t  eFork, eJoin;
    cudaStreamCreateWithFlags(&side, cudaStreamNonBlocking);
    cudaEventCreateWithFlags(&eFork, cudaEventDisableTiming);
    cudaEventCreateWithFlags(&eJoin, cudaEventDisableTiming);

    cudaEventRecord(eFork, (cudaStream_t)0);
    cudaStreamWaitEvent(side, eFork, 0);

    // main: density (long, FMA/LDS-bound)                        -- launch #1
    density_kernel<<<DB_BLKS, HID>>>(mesh, Win, bin, Wblk, bblk, Wout, bout);

    // side: scan prefix (MUFU-bound, independent of density)     -- #2, #3
    pass1_kernel<<<dim3(P1_BLK, C - 1, B), P1_TPB, 0, side>>>(dec, y0, mesh);
    compose_kernel<<<(B * NROWS + 255) / 256, 256, 0, side>>>(init);
    cudaEventRecord(eJoin, side);

    // join, then the dependent tail on main
    cudaStreamWaitEvent((cudaStream_t)0, eJoin, 0);
    pass2_kernel<<<dim3(P2_BLK, C, B), P2_TPB>>>(dec, y0, mesh);        // #4
    sum_kernel<<<1, 1024>>>();                                          // #5
    fill_mesh_kernel<<<(B * NROWS * 2 + 255) / 256, 256>>>(init, mesh, out); // #6
    fill_dens_kernel<<<(B * NROWS + 255) / 256, 256>>>(out);            // #7
    finalize_kernel<<<(B * T + 255) / 256, 256>>>(out);                 // #8

    cudaEventDestroy(eFork);
    cudaEventDestroy(eJoin);
    cudaStreamDestroy(side);
}

// round 9
// speedup vs baseline: 1.3313x; 1.1369x over previous
#include <cuda_runtime.h>
#include <cuda_bf16.h>
#include <cstdint>

// Problem constants
constexpr int HID   = 256;
constexpr int NROWS = 5151;
constexpr int B     = 8;
constexpr int T     = 2048;
constexpr int NLAYERS = 3;

// Density kernel tiling (R6-best config): 144 blocks ~= 1/SM
constexpr int RB      = 36;
constexpr int DB_BLKS = (NROWS + RB - 1) / RB;   // 144
constexpr int KU      = 8;                        // k-prefetch depth

// Chunked scan config: C=16 for 2x scan parallelism
constexpr int C   = 16;
constexpr int TC  = T / C;        // 128
constexpr int P1_TPB = 128;
constexpr int P1_BLK = (NROWS + P1_TPB - 1) / P1_TPB;   // 41
constexpr int P2_TPB = 64;
constexpr int PPT    = 8;                                // 8 points/thread
constexpr int P2_PTS = P2_TPB * PPT;                     // 512
constexpr int P2_BLK = (NROWS + P2_PTS - 1) / P2_PTS;    // 11
constexpr int NW2    = P2_BLK * (P2_TPB / 32);           // 22

// Output section offsets
constexpr int OFF_BNORM = 0;
constexpr int OFF_DENSB = 16384;
constexpr int OFF_M     = 57592;
constexpr int OFF_IS    = 73976;
constexpr int OFF_MESHB = 115184;

// Scratch (device globals)
__device__ float  g_density[DB_BLKS * RB];
__device__ float  g_inv_sum;
__device__ float2 g_ab[(size_t)B * (C - 1) * NROWS];
__device__ float  g_sstart[(size_t)B * C * NROWS];
__device__ float  g_part[(size_t)B * NW2 * T];

typedef unsigned long long u64;

__device__ __forceinline__ float tanh_fast(float x) {
    float y;
    asm("tanh.approx.f32 %0, %1;" : "=f"(y) : "f"(x));
    return y;
}
__device__ __forceinline__ u64 pack2(float lo, float hi) {
    u64 r; asm("mov.b64 %0, {%1, %2};" : "=l"(r) : "f"(lo), "f"(hi)); return r;
}
__device__ __forceinline__ void unpack2(u64 v, float& lo, float& hi) {
    asm("mov.b64 {%0, %1}, %2;" : "=f"(lo), "=f"(hi) : "l"(v));
}
__device__ __forceinline__ u64 fma2(u64 a, u64 b, u64 c) {
    u64 d; asm("fma.rn.f32x2 %0, %1, %2, %3;" : "=l"(d) : "l"(a), "l"(b), "l"(c)); return d;
}

// ---------------------------------------------------------------------------
// Density MLP: exact R6-best version.  h TRANSPOSED in smem [k][r]; KU=8
// software-pipelined weight prefetch + packed fma.rn.f32x2.
// ---------------------------------------------------------------------------
__global__ __launch_bounds__(HID) void density_kernel(
    const float* __restrict__ mesh, const float* __restrict__ Win,
    const float* __restrict__ bin,  const float* __restrict__ Wblk,
    const float* __restrict__ bblk, const float* __restrict__ Wout,
    const float* __restrict__ bout)
{
    __shared__ float cur[HID * RB];   // [k][r], 36 KB
    const int j    = threadIdx.x;
    const int row0 = blockIdx.x * RB;
    float hcur[RB];

    // ---- input layer ----
    {
        const float w0 = Win[j];
        const float w1 = Win[HID + j];
        const float bj = bin[j];
        #pragma unroll
        for (int r = 0; r < RB; r++) {
            const int rr = row0 + r;
            float m0 = 0.f, m1 = 0.f;
            if (rr < NROWS) { m0 = mesh[2 * rr]; m1 = mesh[2 * rr + 1]; }
            hcur[r] = fmaxf(fmaf(m1, w1, fmaf(m0, w0, bj)), 0.f);
        }
    }
    #pragma unroll
    for (int r = 0; r < RB; r += 4)
        *reinterpret_cast<float4*>(cur + j * RB + r) =
            make_float4(hcur[r], hcur[r + 1], hcur[r + 2], hcur[r + 3]);
    __syncthreads();

    // ---- residual layers ----
    for (int l = 0; l < NLAYERS; l++) {
        const float* Wj = Wblk + (size_t)l * HID * HID + j;
        const float  bl = bblk[l * HID + j];

        u64 acc2[RB / 2];
        #pragma unroll
        for (int q = 0; q < RB / 2; q++) acc2[q] = 0ull;

        float wbuf[KU];
        #pragma unroll
        for (int kk = 0; kk < KU; kk++) wbuf[kk] = Wj[(size_t)kk * HID];

        #pragma unroll 1
        for (int k0 = 0; k0 < HID; k0 += KU) {
            float wn[KU];
            const bool more = (k0 + KU) < HID;
            #pragma unroll
            for (int kk = 0; kk < KU; kk++)
                wn[kk] = more ? Wj[(size_t)(k0 + KU + kk) * HID] : 0.f;

            #pragma unroll
            for (int kk = 0; kk < KU; kk++) {
                const u64 w2 = pack2(wbuf[kk], wbuf[kk]);
                const ulonglong2* hp =
                    reinterpret_cast<const ulonglong2*>(cur + (k0 + kk) * RB);
                #pragma unroll
                for (int q = 0; q < RB / 4; q++) {          // 9 LDS.128 per k
                    const ulonglong2 h2 = hp[q];
                    acc2[2 * q]     = fma2(h2.x, w2, acc2[2 * q]);
                    acc2[2 * q + 1] = fma2(h2.y, w2, acc2[2 * q + 1]);
                }
            }
            #pragma unroll
            for (int kk = 0; kk < KU; kk++) wbuf[kk] = wn[kk];
        }

        #pragma unroll
        for (int q = 0; q < RB / 2; q++) {
            float a0, a1;
            unpack2(acc2[q], a0, a1);
            hcur[2 * q]     += fmaxf(a0 + bl, 0.f);
            hcur[2 * q + 1] += fmaxf(a1 + bl, 0.f);
        }

        __syncthreads();
        #pragma unroll
        for (int r = 0; r < RB; r += 4)
            *reinterpret_cast<float4*>(cur + j * RB + r) =
                make_float4(hcur[r], hcur[r + 1], hcur[r + 2], hcur[r + 3]);
        __syncthreads();
    }

    // ---- output layer ----
    {
        const float wo = Wout[j];
        #pragma unroll
        for (int r = 0; r < RB; r += 4)
            *reinterpret_cast<float4*>(cur + j * RB + r) =
                make_float4(hcur[r] * wo, hcur[r + 1] * wo, hcur[r + 2] * wo, hcur[r + 3] * wo);
        __syncthreads();
        if (j < RB) {
            float s0 = bout[0], s1 = 0.f, s2 = 0.f, s3 = 0.f;
            #pragma unroll 4
            for (int k = 0; k < HID; k += 4) {
                s0 += cur[(k + 0) * RB + j];
                s1 += cur[(k + 1) * RB + j];
                s2 += cur[(k + 2) * RB + j];
                s3 += cur[(k + 3) * RB + j];
            }
            const float s  = (s0 + s1) + (s2 + s3);
            const int   rr = row0 + j;
            if (rr < NROWS)
                g_density[rr] = __fdividef(1.f, 1.f + __expf(-s));
        }
    }
}

// ---------------------------------------------------------------------------
// 1/sum(density): single block, float4-vectorized, deterministic
// ---------------------------------------------------------------------------
__global__ __launch_bounds__(1024) void sum_kernel()
{
    __shared__ float sh[32];
    const float4* p4 = reinterpret_cast<const float4*>(g_density);
    float s = 0.f;
    for (int i = threadIdx.x; i < NROWS / 4; i += 1024) {
        const float4 v = p4[i];
        s += (v.x + v.y) + (v.z + v.w);
    }
    if (threadIdx.x < (NROWS & 3))
        s += g_density[(NROWS & ~3) + threadIdx.x];
    #pragma unroll
    for (int o = 16; o; o >>= 1) s += __shfl_xor_sync(0xffffffffu, s, o);
    if ((threadIdx.x & 31) == 0) sh[threadIdx.x >> 5] = s;
    __syncthreads();
    if (threadIdx.x < 32) {
        s = sh[threadIdx.x];
        #pragma unroll
        for (int o = 16; o; o >>= 1) s += __shfl_xor_sync(0xffffffffu, s, o);
        if (threadIdx.x == 0) g_inv_sum = __fdividef(1.f, s);
    }
}

// ---------------------------------------------------------------------------
// Pass 1: per-chunk composed affine transform.  inc is warp-uniform ->
// coherent branch instead of per-point SELs.
// ---------------------------------------------------------------------------
__global__ __launch_bounds__(P1_TPB) void pass1_kernel(
    const float* __restrict__ dec, const float* __restrict__ y0,
    const float* __restrict__ mesh)
{
    __shared__ float hs[TC];
    const int b  = blockIdx.z;
    const int ck = blockIdx.y;
    const int i  = blockIdx.x * P1_TPB + threadIdx.x;
    const int t0 = ck * TC;

    for (int t = threadIdx.x; t < TC; t += P1_TPB) hs[t] = dec[b * T + t0 + t];

    float na2 = 0.f, nb2 = 0.f;
    if (i < NROWS) {
        nb2 = -mesh[2 * i] * 500.f;
        na2 = -mesh[2 * i + 1] * 500.f;
    }
    __syncthreads();

    float hprev = (ck == 0) ? y0[b] : dec[b * T + t0 - 1];
    float A = 1.f, Bc = 0.f;

    #pragma unroll 4
    for (int t = 0; t < TC; t++) {
        const float ht = hs[t];
        float a, bb;
        if (ht >= hprev) {          // warp-uniform branch
            const float u = tanh_fast(fmaf(ht, 500.f, na2));
            a  = fmaf(-0.5f, u, 0.5f);
            bb = fmaf(0.5f, u, 0.5f);
        } else {
            const float u = tanh_fast(fmaf(ht, 500.f, nb2));
            a  = fmaf(0.5f, u, 0.5f);
            bb = fmaf(0.5f, u, -0.5f);
        }
        hprev = ht;
        A  = A * a;
        Bc = fmaf(a, Bc, bb);
    }
    if (i < NROWS)
        g_ab[((size_t)b * (C - 1) + ck) * NROWS + i] = make_float2(A, Bc);
}

// ---------------------------------------------------------------------------
// Compose chunk transforms -> chunk start states
// ---------------------------------------------------------------------------
__global__ __launch_bounds__(256) void compose_kernel(const float* __restrict__ s0_all)
{
    const int idx = blockIdx.x * blockDim.x + threadIdx.x;
    if (idx >= B * NROWS) return;
    const int b = idx / NROWS;
    const int i = idx - b * NROWS;
    float s = s0_all[idx];
    g_sstart[((size_t)b * C + 0) * NROWS + i] = s;
    #pragma unroll
    for (int ck = 0; ck < C - 1; ck++) {
        const float2 ab = g_ab[((size_t)b * (C - 1) + ck) * NROWS + i];
        s = fmaf(ab.x, s, ab.y);
        g_sstart[((size_t)b * C + ck + 1) * NROWS + i] = s;
    }
}

// ---------------------------------------------------------------------------
// Pass 2: replay chunks, fused density dot.  PPT=8, warp-uniform branch.
// ---------------------------------------------------------------------------
__global__ __launch_bounds__(P2_TPB) void pass2_kernel(
    const float* __restrict__ dec, const float* __restrict__ y0,
    const float* __restrict__ mesh)
{
    __shared__ float hs[TC];
    const int b   = blockIdx.z;
    const int ck  = blockIdx.y;
    const int t0  = ck * TC;
    const int i0  = blockIdx.x * P2_PTS;
    const int w   = threadIdx.x >> 5;
    const int lane= threadIdx.x & 31;

    for (int t = threadIdx.x; t < TC; t += P2_TPB) hs[t] = dec[b * T + t0 + t];

    float na2[PPT], nb2[PPT], d[PPT], s[PPT];
    #pragma unroll
    for (int p = 0; p < PPT; p++) {
        const int i = i0 + w * (32 * PPT) + p * 32 + lane;
        if (i < NROWS) {
            nb2[p] = -mesh[2 * i] * 500.f;
            na2[p] = -mesh[2 * i + 1] * 500.f;
            d[p]   = g_density[i];
            s[p]   = g_sstart[((size_t)b * C + ck) * NROWS + i];
        } else { nb2[p] = 0.f; na2[p] = 0.f; d[p] = 0.f; s[p] = 0.f; }
    }
    __syncthreads();

    float hprev = (ck == 0) ? y0[b] : dec[b * T + t0 - 1];
    float* mypart = g_part + ((size_t)(b * NW2 + blockIdx.x * 2 + w)) * T + t0;

    #pragma unroll 2
    for (int t = 0; t < TC; t++) {
        const float ht = hs[t];
        float acc = 0.f;
        if (ht >= hprev) {          // warp-uniform branch
            #pragma unroll
            for (int p = 0; p < PPT; p++) {
                const float u = tanh_fast(fmaf(ht, 500.f, na2[p]));
                s[p] = fmaf(fmaf(-0.5f, u, 0.5f), s[p], fmaf(0.5f, u, 0.5f));
                acc  = fmaf(d[p], s[p], acc);
            }
        } else {
            #pragma unroll
            for (int p = 0; p < PPT; p++) {
                const float u = tanh_fast(fmaf(ht, 500.f, nb2[p]));
                s[p] = fmaf(fmaf(0.5f, u, 0.5f), s[p], fmaf(0.5f, u, -0.5f));
                acc  = fmaf(d[p], s[p], acc);
            }
        }
        hprev = ht;
        #pragma unroll
        for (int o = 16; o; o >>= 1) acc += __shfl_xor_sync(0xffffffffu, acc, o);
        if (lane == 0) mypart[t] = acc;
    }
}

// ---------------------------------------------------------------------------
// Reduce warp partials -> m, b_norm
// ---------------------------------------------------------------------------
__global__ __launch_bounds__(256) void finalize_kernel(float* __restrict__ out)
{
    const int idx = blockIdx.x * blockDim.x + threadIdx.x;
    if (idx >= B * T) return;
    const int b = idx / T;
    const int t = idx - b * T;
    const float* p = g_part + (size_t)b * NW2 * T + t;
    float s0 = 0.f, s1 = 0.f;
    #pragma unroll 2
    for (int wv = 0; wv < NW2; wv += 2) {
        s0 += p[(size_t)wv * T];
        s1 += p[(size_t)(wv + 1) * T];
    }
    const float m = (s0 + s1) * g_inv_sum;
    out[OFF_BNORM + idx] = fmaf(0.5f, m, 0.5f);
    out[OFF_M + idx]     = m;
}

// ---------------------------------------------------------------------------
// fill_mesh: input-only sections; fill_dens: density broadcast
// ---------------------------------------------------------------------------
__global__ __launch_bounds__(256) void fill_mesh_kernel(
    const float* __restrict__ s0_all, const float* __restrict__ mesh,
    float* __restrict__ out)
{
    const int i = blockIdx.x * blockDim.x + threadIdx.x;
    if (i < B * NROWS)
        out[OFF_IS + i] = s0_all[i];
    if (i < B * NROWS * 2)
        out[OFF_MESHB + i] = mesh[i % (2 * NROWS)];
}

__global__ __launch_bounds__(256) void fill_dens_kernel(float* __restrict__ out)
{
    const int i = blockIdx.x * blockDim.x + threadIdx.x;
    if (i < B * NROWS)
        out[OFF_DENSB + i] = g_density[i % NROWS];
}

// ---------------------------------------------------------------------------
// Schedule:
//   main: density ──────────────┐(eD)          join(eJ)→ pass2 → wait(eS) → finalize
//   side: pass1 → compose ──────┘(eJ)  wait(eD)→ sum → fill_dens → fill_mesh (eS)
// Critical path: density → pass2 → finalize; everything else overlapped.
// ---------------------------------------------------------------------------
extern "C" void kernel_launch(void* const* d_in, const int* in_sizes, int n_in,
                              void* d_out, int out_size)
{
    (void)in_sizes; (void)n_in; (void)out_size;
    const float* dec  = (const float*)d_in[1];
    const float* init = (const float*)d_in[2];
    const float* y0   = (const float*)d_in[3];
    const float* mesh = (const float*)d_in[4];
    const float* Win  = (const float*)d_in[5];
    const float* bin  = (const float*)d_in[6];
    const float* Wblk = (const float*)d_in[7];
    const float* bblk = (const float*)d_in[8];
    const float* Wout = (const float*)d_in[9];
    const float* bout = (const float*)d_in[10];
    float* out = (float*)d_out;

    cudaStream_t side;
    cudaEvent_t  eFork, eD, eJ, eS;
    cudaStreamCreateWithFlags(&side, cudaStreamNonBlocking);
    cudaEventCreateWithFlags(&eFork, cudaEventDisableTiming);
    cudaEventCreateWithFlags(&eD, cudaEventDisableTiming);
    cudaEventCreateWithFlags(&eJ, cudaEventDisableTiming);
    cudaEventCreateWithFlags(&eS, cudaEventDisableTiming);

    cudaEventRecord(eFork, (cudaStream_t)0);
    cudaStreamWaitEvent(side, eFork, 0);

    // main: density                                             -- launch #1
    density_kernel<<<DB_BLKS, HID>>>(mesh, Win, bin, Wblk, bblk, Wout, bout);
    cudaEventRecord(eD, (cudaStream_t)0);

    // side: scan prefix (independent of density)                -- #2, #3
    pass1_kernel<<<dim3(P1_BLK, C - 1, B), P1_TPB, 0, side>>>(dec, y0, mesh);
    compose_kernel<<<(B * NROWS + 255) / 256, 256, 0, side>>>(init);
    cudaEventRecord(eJ, side);

    // main: join scan prefix, run pass2                         -- #4
    cudaStreamWaitEvent((cudaStream_t)0, eJ, 0);
    pass2_kernel<<<dim3(P2_BLK, C, B), P2_TPB>>>(dec, y0, mesh);

    // side: after density -> sum + fills (overlap with pass2)   -- #5..#7
    cudaStreamWaitEvent(side, eD, 0);
    sum_kernel<<<1, 1024, 0, side>>>();
    fill_dens_kernel<<<(B * NROWS + 255) / 256, 256, 0, side>>>(out);
    fill_mesh_kernel<<<(B * NROWS * 2 + 255) / 256, 256, 0, side>>>(init, mesh, out);
    cudaEventRecord(eS, side);

    // main: finalize after pass2 + sum                          -- #8
    cudaStreamWaitEvent((cudaStream_t)0, eS, 0);
    finalize_kernel<<<(B * T + 255) / 256, 256>>>(out);

    cudaEventDestroy(eFork);
    cudaEventDestroy(eD);
    cudaEventDestroy(eJ);
    cudaEventDestroy(eS);
    cudaStreamDestroy(side);
}